// round 14
// baseline (speedup 1.0000x reference)
#include <cuda_runtime.h>
#include <cuda_bf16.h>
#include <cstdint>

#define Bz 64
#define Tz 512
#define Iz 128
#define Hz 512
#define Gz 2048          // 4*H
#define BTz (Bz*Tz)      // 32768
#define BHs (Bz*Hz)      // 32768

#define NBLK 128
#define PNT 512          // persistent kernel threads (16 warps)
#define GRP 32           // blocks per bg barrier group

// Scratch (static device globals)
__device__ float g_XG[(size_t)BTz * Gz];            // 256 MiB: gate projections
__device__ __nv_bfloat16 g_AH[(size_t)BTz * Hz];    // 32 MiB: A hi (x-split, then hseq)
__device__ __nv_bfloat16 g_AL[(size_t)BTz * Hz];    // 32 MiB: A lo
__device__ __nv_bfloat16 g_WH[(size_t)Gz * Hz];     // 2 MiB: w_ih hi
__device__ __nv_bfloat16 g_WL[(size_t)Gz * Hz];     // 2 MiB: w_ih lo
__device__ __nv_bfloat16 g_W2H[(size_t)Gz * Hz];    // 2 MiB: w_hh hi
__device__ __nv_bfloat16 g_W2L[(size_t)Gz * Hz];    // 2 MiB: w_hh lo
// Published hidden state: [pingpong][bg][hi/lo][16 b][520 cols] (512..519 pad)
__device__ __align__(16) __nv_bfloat16 g_HT2[2][4][2][16][520];
// Per-bg monotonic barrier counters, padded to separate 256B lines.
__device__ unsigned g_count4[4 * 64];

// ---------------- async-copy / mma helpers ----------------
__device__ __forceinline__ void cp_async16(void* dst_smem, const void* src_gmem) {
    unsigned d = (unsigned)__cvta_generic_to_shared(dst_smem);
    asm volatile("cp.async.cg.shared.global [%0], [%1], 16;\n"
                 :: "r"(d), "l"(src_gmem));
}
#define CP_COMMIT() asm volatile("cp.async.commit_group;\n" ::: "memory")
#define CP_WAIT0()  asm volatile("cp.async.wait_group 0;\n" ::: "memory")
#define CP_WAIT1()  asm volatile("cp.async.wait_group 1;\n" ::: "memory")

__device__ __forceinline__ void ldsm4(uint32_t* r, const __nv_bfloat16* p) {
    uint32_t a = (uint32_t)__cvta_generic_to_shared(p);
    asm volatile("ldmatrix.sync.aligned.m8n8.x4.shared.b16 {%0,%1,%2,%3}, [%4];"
                 : "=r"(r[0]), "=r"(r[1]), "=r"(r[2]), "=r"(r[3]) : "r"(a));
}

__device__ __forceinline__ void mma16816(float* d, const uint32_t* a, const uint32_t* b) {
    asm volatile(
        "mma.sync.aligned.m16n8k16.row.col.f32.bf16.bf16.f32 "
        "{%0,%1,%2,%3}, {%4,%5,%6,%7}, {%8,%9}, {%0,%1,%2,%3};"
        : "+f"(d[0]), "+f"(d[1]), "+f"(d[2]), "+f"(d[3])
        : "r"(a[0]), "r"(a[1]), "r"(a[2]), "r"(a[3]), "r"(b[0]), "r"(b[1]));
}

__device__ __forceinline__ void mbar_wait(unsigned mbar, unsigned ph) {
    unsigned done;
    asm volatile(
        "{\n\t.reg .pred P;\n\t"
        "mbarrier.try_wait.parity.acquire.cta.shared::cta.b64 P, [%1], %2;\n\t"
        "selp.b32 %0, 1, 0, P;\n\t}"
        : "=r"(done) : "r"(mbar), "r"(ph) : "memory");
    if (!done) {
        asm volatile(
            "{\n\t.reg .pred P1;\n\t"
            "WL%=:\n\t"
            "mbarrier.try_wait.parity.acquire.cta.shared::cta.b64 P1, [%0], %1;\n\t"
            "@P1 bra.uni WD%=;\n\t"
            "bra.uni WL%=;\n\t"
            "WD%=:\n\t}"
            :: "r"(mbar), "r"(ph) : "memory");
    }
}

// ---------------- fast transcendentals (MUFU EX2 path) ----------------
__device__ __forceinline__ float fsig(float x) {
    return __fdividef(1.0f, 1.0f + __expf(-x));
}
__device__ __forceinline__ float ftanh(float x) {
    return __fmaf_rn(2.0f, __fdividef(1.0f, 1.0f + __expf(-2.0f * x)), -1.0f);
}

// ---------------- fp32 -> bf16 hi/lo split ----------------
__global__ __launch_bounds__(256) void split_kernel(
    const float4* __restrict__ src,
    __nv_bfloat162* __restrict__ hi, __nv_bfloat162* __restrict__ lo, int n4)
{
    int i = blockIdx.x * blockDim.x + threadIdx.x;
    if (i >= n4) return;
    float4 v = src[i];
    float xs[4] = {v.x, v.y, v.z, v.w};
    __nv_bfloat16 h[4], l[4];
#pragma unroll
    for (int k = 0; k < 4; k++) {
        h[k] = __float2bfloat16(xs[k]);
        l[k] = __float2bfloat16(xs[k] - __bfloat162float(h[k]));
    }
    __nv_bfloat162 h0; h0.x = h[0]; h0.y = h[1];
    __nv_bfloat162 h1; h1.x = h[2]; h1.y = h[3];
    __nv_bfloat162 l0; l0.x = l[0]; l0.y = l[1];
    __nv_bfloat162 l1; l1.x = l[2]; l1.y = l[3];
    hi[2 * i] = h0; hi[2 * i + 1] = h1;
    lo[2 * i] = l0; lo[2 * i + 1] = l1;
}

// ---------------- tensor-core input-projection GEMM (validated R8) ----------------
__global__ void __launch_bounds__(256, 1) gemm_tc(
    float* __restrict__ C,
    const __nv_bfloat16* __restrict__ Ah, const __nv_bfloat16* __restrict__ Al,
    const __nv_bfloat16* __restrict__ Wh, const __nv_bfloat16* __restrict__ Wl,
    int K, const float* __restrict__ bias0, const float* __restrict__ bias1)
{
    extern __shared__ __nv_bfloat16 sm[];
    const int ARR = 128 * 40;
    const int STG = 4 * ARR;
    const int tid = threadIdx.x;
    const int lane = tid & 31, wid = tid >> 5;
    const int wm = wid & 1, wn = wid >> 1;
    const int bn = blockIdx.x, bm = blockIdx.y;

    const __nv_bfloat16* g0 = Ah + (size_t)(bm * 128) * K;
    const __nv_bfloat16* g1 = Al + (size_t)(bm * 128) * K;
    const __nv_bfloat16* g2 = Wh + (size_t)(bn * 128) * K;
    const __nv_bfloat16* g3 = Wl + (size_t)(bn * 128) * K;
    const __nv_bfloat16* gsrc[4] = {g0, g1, g2, g3};

    const int l_r = tid >> 2;
    const int l_c = tid & 3;

#define LOAD_STAGE(buf, kt)                                                     \
    {                                                                           \
        _Pragma("unroll")                                                       \
        for (int p = 0; p < 8; p++) {                                           \
            const int arr = p >> 1;                                             \
            const int r = (p & 1) * 64 + l_r;                                   \
            const void* s = gsrc[arr] + (size_t)r * K + (kt) + l_c * 8;         \
            void* d = (char*)(sm + (buf) * STG + arr * ARR + r * 40) + l_c * 16;\
            cp_async16(d, s);                                                   \
        }                                                                       \
        CP_COMMIT();                                                            \
    }

    float acc[4][4][4] = {};
    const int nk = K / 32;

    LOAD_STAGE(0, 0);

    const int a_lrow = (lane < 16) ? lane : lane - 16;
    const int a_cb = (lane < 16) ? 0 : 8;
    const int bgrp = lane >> 3, bwi = lane & 7;
    const int b_nrow = ((bgrp >= 2) ? 8 : 0) + bwi;
    const int b_koff = (bgrp & 1) ? 8 : 0;

    for (int it = 0; it < nk; it++) {
        if (it + 1 < nk) {
            LOAD_STAGE((it + 1) & 1, (it + 1) * 32);
            CP_WAIT1();
        } else {
            CP_WAIT0();
        }
        __syncthreads();
        const __nv_bfloat16* S = sm + (it & 1) * STG;

#pragma unroll
        for (int kk = 0; kk < 32; kk += 16) {
            uint32_t ah[4][4], al[4][4];
#pragma unroll
            for (int mt = 0; mt < 4; mt++) {
                int row = wm * 64 + mt * 16 + a_lrow;
                ldsm4(ah[mt], S + row * 40 + kk + a_cb);
                ldsm4(al[mt], S + ARR + row * 40 + kk + a_cb);
            }
            uint32_t bh[4][2], bl[4][2];
#pragma unroll
            for (int pr = 0; pr < 2; pr++) {
                int nrow = wn * 32 + pr * 16 + b_nrow;
                uint32_t r[4];
                ldsm4(r, S + 2 * ARR + nrow * 40 + kk + b_koff);
                bh[pr * 2][0] = r[0]; bh[pr * 2][1] = r[1];
                bh[pr * 2 + 1][0] = r[2]; bh[pr * 2 + 1][1] = r[3];
                ldsm4(r, S + 3 * ARR + nrow * 40 + kk + b_koff);
                bl[pr * 2][0] = r[0]; bl[pr * 2][1] = r[1];
                bl[pr * 2 + 1][0] = r[2]; bl[pr * 2 + 1][1] = r[3];
            }
#pragma unroll
            for (int mt = 0; mt < 4; mt++)
#pragma unroll
                for (int nt = 0; nt < 4; nt++) {
                    mma16816(acc[mt][nt], ah[mt], bh[nt]);
                    mma16816(acc[mt][nt], ah[mt], bl[nt]);
                    mma16816(acc[mt][nt], al[mt], bh[nt]);
                }
        }
        __syncthreads();
    }

    const int erow = lane >> 2, ecol = (lane & 3) * 2;
#pragma unroll
    for (int mt = 0; mt < 4; mt++) {
        int gr = bm * 128 + wm * 64 + mt * 16 + erow;
#pragma unroll
        for (int nt = 0; nt < 4; nt++) {
            int gc = bn * 128 + wn * 32 + nt * 8 + ecol;
            float b0v = bias0[gc] + bias1[gc];
            float b1v = bias0[gc + 1] + bias1[gc + 1];
            float2 v0 = make_float2(acc[mt][nt][0] + b0v, acc[mt][nt][1] + b1v);
            float2 v1 = make_float2(acc[mt][nt][2] + b0v, acc[mt][nt][3] + b1v);
            *(float2*)(C + (size_t)gr * Gz + gc) = v0;
            *(float2*)(C + (size_t)(gr + 8) * Gz + gc) = v1;
        }
    }
#undef LOAD_STAGE
}

// ---------------- tensor-core persistent LSTM layer ----------------
// 128 blocks x 512 threads (16 warps). Block (bg = bid>>5, jg = bid&31) owns
// batches [bg*16, bg*16+16) x j-cols [jg*16, jg*16+16). Warp (kh = wid&3,
// ng = wid>>2): kh = K-quarter of 128, ng = 16 gate-cols. bg-local monotonic
// barrier (red.release + acquire poll); hi/lo plane bulk copies with separate
// mbarriers; pass1 (ah*bh) on hi arrival, pass2 on lo; w-hi frags in regs.
// No block-wide sync after the tid0 barrier region: consumer warps proceed
// straight to the next parity wait, overlapping the tid0 L2 poll.
__global__ void __launch_bounds__(PNT, 1) lstm_layer_tc(
    const __nv_bfloat16* __restrict__ wqh,   // [2048][512] w_hh hi
    const __nv_bfloat16* __restrict__ wql,   // lo
    const float* __restrict__ xg,            // [B*T][2048] (+biases)
    const float* __restrict__ hxl, const float* __restrict__ cxl,
    __nv_bfloat16* __restrict__ hseq_hi,     // [B*T][512] or nullptr
    __nv_bfloat16* __restrict__ hseq_lo,
    float* __restrict__ hn_out, float* __restrict__ cn_out)
{
    extern __shared__ __nv_bfloat16 sm[];
    __nv_bfloat16* w_hi = sm;                 // [64 q][520]
    __nv_bfloat16* w_lo = sm + 64 * 520;
    __nv_bfloat16* h_hi = sm + 128 * 520;     // [16 b][520]  (hi bulk-copy dest)
    __nv_bfloat16* h_lo = sm + 144 * 520;     // [16 b][520]  (lo bulk-copy dest)
    float* acc_s = (float*)(sm + 160 * 520);  // [4 kh][64 q][16 b]
    __nv_bfloat16* pub_s = (__nv_bfloat16*)(acc_s + 4 * 64 * 16); // [2][16][16]

    __shared__ __align__(16) unsigned long long s_mbar[2];

    const int tid = threadIdx.x;
    const int bid = blockIdx.x;
    const int bg = bid >> 5;
    const int jg = bid & 31;
    const int lane = tid & 31, wid = tid >> 5;
    const int kh = wid & 3, ng = wid >> 2;

    unsigned* cnt = &g_count4[bg * 64];

    const unsigned mbar0 = (unsigned)__cvta_generic_to_shared(&s_mbar[0]);
    const unsigned mbar1 = (unsigned)__cvta_generic_to_shared(&s_mbar[1]);
    const unsigned hdst_hi = (unsigned)__cvta_generic_to_shared(h_hi);
    const unsigned hdst_lo = (unsigned)__cvta_generic_to_shared(h_lo);
    const unsigned PLBYTES = 16 * 520 * 2;   // 16,640 B per plane

    if (tid == 0) {
        asm volatile("mbarrier.init.shared.b64 [%0], 1;" :: "r"(mbar0) : "memory");
        asm volatile("mbarrier.init.shared.b64 [%0], 1;" :: "r"(mbar1) : "memory");
    }

    // ---- load w_hh slice (hi+lo) via cp.async: one-time ----
    for (int i = tid; i < 8192; i += PNT) {
        int arr = i >> 12;
        int idx = i & 4095;
        int q = idx >> 6, c = idx & 63;
        int gr = (q >> 4) * 512 + jg * 16 + (q & 15);
        const __nv_bfloat16* src = (arr ? wql : wqh) + (size_t)gr * Hz + c * 8;
        __nv_bfloat16* dst = (arr ? w_lo : w_hi) + q * 520 + c * 8;
        cp_async16(dst, src);
    }
    CP_COMMIT();

    // ---- cell identity + init state; publish h0 into padded buffer ----
    const int b_loc = tid & 15, jj = (tid >> 4) & 15;
    const int b_glob = bg * 16 + b_loc;
    const int j_glob = jg * 16 + jj;
    float c_reg = 0.0f;
    if (tid < 256) {
        c_reg = cxl[b_glob * Hz + j_glob];
        float h0 = hxl[b_glob * Hz + j_glob];
        __nv_bfloat16 hh0 = __float2bfloat16(h0);
        __nv_bfloat16 hl0 = __float2bfloat16(h0 - __bfloat162float(hh0));
        g_HT2[0][bg][0][b_loc][j_glob] = hh0;
        g_HT2[0][bg][1][b_loc][j_glob] = hl0;
    }
    CP_WAIT0();

    // ---- initial barrier (nbar=1) + issue copies for t=0 ----
    unsigned nbar = 1;
    __syncthreads();
    if (tid == 0) {
        asm volatile("red.release.gpu.global.add.u32 [%0], %1;"
                     :: "l"(cnt), "r"(1u) : "memory");
        unsigned v;
        do {
            asm volatile("ld.acquire.gpu.u32 %0, [%1];" : "=r"(v) : "l"(cnt) : "memory");
        } while (v < nbar * GRP);
        asm volatile("mbarrier.arrive.expect_tx.shared.b64 _, [%0], %1;"
                     :: "r"(mbar0), "r"(PLBYTES) : "memory");
        asm volatile(
            "cp.async.bulk.shared::cta.global.mbarrier::complete_tx::bytes "
            "[%0], [%1], %2, [%3];"
            :: "r"(hdst_hi), "l"(&g_HT2[0][bg][0][0][0]),
               "r"(PLBYTES), "r"(mbar0) : "memory");
        asm volatile("mbarrier.arrive.expect_tx.shared.b64 _, [%0], %1;"
                     :: "r"(mbar1), "r"(PLBYTES) : "memory");
        asm volatile(
            "cp.async.bulk.shared::cta.global.mbarrier::complete_tx::bytes "
            "[%0], [%1], %2, [%3];"
            :: "r"(hdst_lo), "l"(&g_HT2[0][bg][1][0][0]),
               "r"(PLBYTES), "r"(mbar1) : "memory");
    }
    __syncthreads();     // also orders the w-smem fill before whf preload

    // ---- fragment identities (identical to validated gemm_tc) ----
    const int a_lrow = (lane < 16) ? lane : lane - 16;
    const int a_cb = (lane < 16) ? 0 : 8;
    const int bgrp = lane >> 3, bwi = lane & 7;
    const int b_nrow = ((bgrp >= 2) ? 8 : 0) + bwi;
    const int b_koff = (bgrp & 1) ? 8 : 0;
    const int erow = lane >> 2, ecol = (lane & 3) * 2;

    const __nv_bfloat16* wrow_hi = w_hi + (ng * 16 + b_nrow) * 520 + b_koff;
    const __nv_bfloat16* wrow_lo = w_lo + (ng * 16 + b_nrow) * 520 + b_koff;
    const __nv_bfloat16* arow_hi = h_hi + a_lrow * 520 + a_cb;
    const __nv_bfloat16* arow_lo = h_lo + a_lrow * 520 + a_cb;

    const int kbase = kh * 128;

    // ---- preload loop-invariant w-hi fragments into registers ----
    uint32_t whf[8][4];
#pragma unroll
    for (int ks = 0; ks < 8; ks++)
        ldsm4(whf[ks], wrow_hi + kbase + ks * 16);

    float hlast = 0.0f;
    unsigned ph = 0;

    for (int t = 0; t < Tz; t++) {
        const int p = t & 1;

        // ---- prefetch xg for cell threads (overlaps in-flight copies) ----
        float xp[4];
        if (tid < 256) {
#pragma unroll
            for (int g = 0; g < 4; g++)
                xp[g] = xg[((size_t)b_glob * Tz + t) * Gz + g * 512 + j_glob];
        }

        float acc0[4] = {}, acc1[4] = {};
        uint32_t ahf[8][4];

        // ---- pass 1: ah * bh (hi plane only, w-hi resident in regs) ----
        mbar_wait(mbar0, ph);
#pragma unroll
        for (int ks = 0; ks < 8; ks++) {
            int k = kbase + ks * 16;
            ldsm4(ahf[ks], arow_hi + k);
            mma16816(acc0, ahf[ks], &whf[ks][0]);
            mma16816(acc1, ahf[ks], &whf[ks][2]);
        }

        // ---- pass 2: al * bh + ah * bl (needs lo plane) ----
        mbar_wait(mbar1, ph);
        ph ^= 1;
#pragma unroll
        for (int ks = 0; ks < 8; ks++) {
            int k = kbase + ks * 16;
            uint32_t al[4], rl[4];
            ldsm4(al, arow_lo + k);
            ldsm4(rl, wrow_lo + k);
            uint32_t bl0[2] = {rl[0], rl[1]}, bl1[2] = {rl[2], rl[3]};
            mma16816(acc0, al, &whf[ks][0]);
            mma16816(acc1, al, &whf[ks][2]);
            mma16816(acc0, ahf[ks], bl0);
            mma16816(acc1, ahf[ks], bl1);
        }

        // ---- stash K-quarter partials: acc_s[kh][q][b] ----
        {
            int q0 = ng * 16 + ecol;
            acc_s[(kh * 64 + q0) * 16 + erow]         = acc0[0];
            acc_s[(kh * 64 + q0 + 1) * 16 + erow]     = acc0[1];
            acc_s[(kh * 64 + q0) * 16 + erow + 8]     = acc0[2];
            acc_s[(kh * 64 + q0 + 1) * 16 + erow + 8] = acc0[3];
            int q1 = ng * 16 + 8 + ecol;
            acc_s[(kh * 64 + q1) * 16 + erow]         = acc1[0];
            acc_s[(kh * 64 + q1 + 1) * 16 + erow]     = acc1[1];
            acc_s[(kh * 64 + q1) * 16 + erow + 8]     = acc1[2];
            acc_s[(kh * 64 + q1 + 1) * 16 + erow + 8] = acc1[3];
        }
        __syncthreads();

        // ---- cell update (threads 0..255): fast gates, stage publish ----
        __nv_bfloat16 hh, hl;
        if (tid < 256) {
            float gv[4];
#pragma unroll
            for (int g = 0; g < 4; g++) {
                int q = g * 16 + jj;
                float s = xp[g];
#pragma unroll
                for (int z = 0; z < 4; z++)
                    s += acc_s[(z * 64 + q) * 16 + b_loc];
                gv[g] = s;
            }
            float ig = fsig(gv[0]);
            float fg = fsig(gv[1]);
            float gg = ftanh(gv[2]);
            float og = fsig(gv[3]);
            c_reg = fg * c_reg + ig * gg;
            float hnew = og * ftanh(c_reg);
            hlast = hnew;
            hh = __float2bfloat16(hnew);
            hl = __float2bfloat16(hnew - __bfloat162float(hh));
            pub_s[(0 * 16 + b_loc) * 16 + jj] = hh;
            pub_s[(1 * 16 + b_loc) * 16 + jj] = hl;
        }
        __syncthreads();

        // ---- coalesced publish: 64 x STG.128 ----
        if (tid < 64) {
            int plane = tid >> 5;
            int b = (tid >> 1) & 15;
            int half = tid & 1;
            uint4 v = *(uint4*)(pub_s + plane * 256 + b * 16 + half * 8);
            *(uint4*)(&g_HT2[p ^ 1][bg][plane][b][jg * 16 + half * 8]) = v;
        }

        // ---- fused barrier + next copy issue (no trailing block sync) ----
        if (t < Tz - 1) {
            nbar++;
            __syncthreads();        // publish visible before tid0's release
            if (tid == 0) {
                asm volatile("red.release.gpu.global.add.u32 [%0], %1;"
                             :: "l"(cnt), "r"(1u) : "memory");
                unsigned v;
                do {
                    asm volatile("ld.acquire.gpu.u32 %0, [%1];" : "=r"(v) : "l"(cnt) : "memory");
                } while (v < nbar * GRP);
                asm volatile("mbarrier.arrive.expect_tx.shared.b64 _, [%0], %1;"
                             :: "r"(mbar0), "r"(PLBYTES) : "memory");
                asm volatile(
                    "cp.async.bulk.shared::cta.global.mbarrier::complete_tx::bytes "
                    "[%0], [%1], %2, [%3];"
                    :: "r"(hdst_hi), "l"(&g_HT2[p ^ 1][bg][0][0][0]),
                       "r"(PLBYTES), "r"(mbar0) : "memory");
                asm volatile("mbarrier.arrive.expect_tx.shared.b64 _, [%0], %1;"
                             :: "r"(mbar1), "r"(PLBYTES) : "memory");
                asm volatile(
                    "cp.async.bulk.shared::cta.global.mbarrier::complete_tx::bytes "
                    "[%0], [%1], %2, [%3];"
                    :: "r"(hdst_lo), "l"(&g_HT2[p ^ 1][bg][1][0][0]),
                       "r"(PLBYTES), "r"(mbar1) : "memory");
            }
            // consumer warps fall through to next iteration's mbar_wait;
            // hseq stores below overlap tid0's poll.
        }

        // ---- hseq store (off the release path) ----
        if (hseq_hi && tid < 256) {
            size_t off = ((size_t)b_glob * Tz + t) * Hz + j_glob;
            hseq_hi[off] = hh;
            hseq_lo[off] = hl;
        }
    }

    if (tid < 256) {
        hn_out[b_glob * Hz + j_glob] = hlast;
        cn_out[b_glob * Hz + j_glob] = c_reg;
    }

    if (tid == 0) {
        asm volatile("mbarrier.inval.shared.b64 [%0];" :: "r"(mbar0) : "memory");
        asm volatile("mbarrier.inval.shared.b64 [%0];" :: "r"(mbar1) : "memory");
    }

    // ---- exit protocol: restore counter to 0 for graph replay ----
    __syncthreads();
    if (tid == 0) {
        atomicAdd(cnt, 1u);
        if (jg == 0) {
            const unsigned exit_target = (512u + 1u) * GRP;   // 16416
            unsigned v;
            do {
                asm volatile("ld.acquire.gpu.u32 %0, [%1];" : "=r"(v) : "l"(cnt) : "memory");
            } while (v < exit_target);
            asm volatile("st.relaxed.gpu.u32 [%0], %1;" :: "l"(cnt), "r"(0u) : "memory");
        }
    }
}

// ---------------- FC head ----------------
__global__ __launch_bounds__(256) void fc_kernel(
    float* __restrict__ out, const float* __restrict__ h,
    const float* __restrict__ w, const float* __restrict__ bb)
{
    int b = blockIdx.x;
    float s = 0.0f;
    for (int k = threadIdx.x; k < Hz; k += blockDim.x)
        s += h[(size_t)b * Hz + k] * w[k];
#pragma unroll
    for (int o = 16; o > 0; o >>= 1)
        s += __shfl_xor_sync(0xFFFFFFFFu, s, o);
    __shared__ float red[8];
    int wid = threadIdx.x >> 5, lane = threadIdx.x & 31;
    if (lane == 0) red[wid] = s;
    __syncthreads();
    if (threadIdx.x == 0) {
        float t = 0.0f;
#pragma unroll
        for (int i = 0; i < 8; i++) t += red[i];
        out[b] = t + bb[0];
    }
}

extern "C" void kernel_launch(void* const* d_in, const int* in_sizes, int n_in,
                              void* d_out, int out_size) {
    (void)in_sizes; (void)n_in; (void)out_size;
    const float* x    = (const float*)d_in[0];
    const float* hx   = (const float*)d_in[1];
    const float* cx   = (const float*)d_in[2];
    const float* wih0 = (const float*)d_in[3];
    const float* whh0 = (const float*)d_in[4];
    const float* bih0 = (const float*)d_in[5];
    const float* bhh0 = (const float*)d_in[6];
    const float* wih1 = (const float*)d_in[7];
    const float* whh1 = (const float*)d_in[8];
    const float* bih1 = (const float*)d_in[9];
    const float* bhh1 = (const float*)d_in[10];
    const float* fcw  = (const float*)d_in[11];
    const float* fcb  = (const float*)d_in[12];
    float* out = (float*)d_out;

    void *vXG, *vAH, *vAL, *vWH, *vWL, *vW2H, *vW2L;
    cudaGetSymbolAddress(&vXG, g_XG);
    cudaGetSymbolAddress(&vAH, g_AH);
    cudaGetSymbolAddress(&vAL, g_AL);
    cudaGetSymbolAddress(&vWH, g_WH);
    cudaGetSymbolAddress(&vWL, g_WL);
    cudaGetSymbolAddress(&vW2H, g_W2H);
    cudaGetSymbolAddress(&vW2L, g_W2L);
    float* XG = (float*)vXG;
    __nv_bfloat16* AH = (__nv_bfloat16*)vAH;
    __nv_bfloat16* AL = (__nv_bfloat16*)vAL;
    __nv_bfloat16* WH = (__nv_bfloat16*)vWH;
    __nv_bfloat16* WL = (__nv_bfloat16*)vWL;
    __nv_bfloat16* W2H = (__nv_bfloat16*)vW2H;
    __nv_bfloat16* W2L = (__nv_bfloat16*)vW2L;

    const int gemm_smem = 2 * 4 * 128 * 40 * (int)sizeof(__nv_bfloat16);   // 80 KB
    const int persist_smem = 160 * 520 * (int)sizeof(__nv_bfloat16)
                           + 4 * 64 * 16 * (int)sizeof(float)
                           + 2 * 16 * 16 * (int)sizeof(__nv_bfloat16);     // ~183.8 KB
    static bool attr_set = false;
    if (!attr_set) {
        cudaFuncSetAttribute(gemm_tc,
                             cudaFuncAttributeMaxDynamicSharedMemorySize, gemm_smem);
        cudaFuncSetAttribute(lstm_layer_tc,
                             cudaFuncAttributeMaxDynamicSharedMemorySize, persist_smem);
        attr_set = true;
    }

    // Output packing: [out(64) | hn(2*B*H) | cn(2*B*H)]
    float* hn = out + Bz;
    float* cn = out + Bz + 2 * BHs;

    // ---- Layer 0 ----
    {
        int n4 = (BTz * Iz) / 4;
        split_kernel<<<(n4 + 255) / 256, 256>>>(
            (const float4*)x, (__nv_bfloat162*)AH, (__nv_bfloat162*)AL, n4);
    }
    {
        int n4 = (Gz * Iz) / 4;
        split_kernel<<<(n4 + 255) / 256, 256>>>(
            (const float4*)wih0, (__nv_bfloat162*)WH, (__nv_bfloat162*)WL, n4);
    }
    {
        int n4 = (Gz * Hz) / 4;
        split_kernel<<<(n4 + 255) / 256, 256>>>(
            (const float4*)whh0, (__nv_bfloat162*)W2H, (__nv_bfloat162*)W2L, n4);
    }
    gemm_tc<<<dim3(Gz / 128, BTz / 128), 256, gemm_smem>>>(
        XG, AH, AL, WH, WL, Iz, bih0, bhh0);
    lstm_layer_tc<<<NBLK, PNT, persist_smem>>>(
        W2H, W2L, XG, hx, cx, AH, AL, hn, cn);   // hseq -> AH/AL for GEMM1

    // ---- Layer 1 ----
    {
        int n4 = (Gz * Hz) / 4;
        split_kernel<<<(n4 + 255) / 256, 256>>>(
            (const float4*)wih1, (__nv_bfloat162*)WH, (__nv_bfloat162*)WL, n4);
        split_kernel<<<(n4 + 255) / 256, 256>>>(
            (const float4*)whh1, (__nv_bfloat162*)W2H, (__nv_bfloat162*)W2L, n4);
    }
    gemm_tc<<<dim3(Gz / 128, BTz / 128), 256, gemm_smem>>>(
        XG, AH, AL, WH, WL, Hz, bih1, bhh1);
    lstm_layer_tc<<<NBLK, PNT, persist_smem>>>(
        W2H, W2L, XG, hx + BHs, cx + BHs, nullptr, nullptr, hn + BHs, cn + BHs);

    // ---- FC head ----
    fc_kernel<<<Bz, 256>>>(out, hn + BHs, fcw, fcb);
}

// round 15
// speedup vs baseline: 1.1075x; 1.1075x over previous
#include <cuda_runtime.h>
#include <cuda_bf16.h>
#include <cstdint>

#define Bz 64
#define Tz 512
#define Iz 128
#define Hz 512
#define Gz 2048          // 4*H
#define BTz (Bz*Tz)      // 32768
#define BHs (Bz*Hz)      // 32768

#define NBLK 128
#define PNT 512          // persistent kernel threads (16 warps)
#define QPROD 8          // producers per (bg, quarter)

// Scratch (static device globals)
__device__ float g_XG[(size_t)BTz * Gz];            // 256 MiB: gate projections
__device__ __nv_bfloat16 g_AH[(size_t)BTz * Hz];    // 32 MiB: A hi (x-split, then hseq)
__device__ __nv_bfloat16 g_AL[(size_t)BTz * Hz];    // 32 MiB: A lo
__device__ __nv_bfloat16 g_WH[(size_t)Gz * Hz];     // 2 MiB: w_ih hi
__device__ __nv_bfloat16 g_WL[(size_t)Gz * Hz];     // 2 MiB: w_ih lo
__device__ __nv_bfloat16 g_W2H[(size_t)Gz * Hz];    // 2 MiB: w_hh hi
__device__ __nv_bfloat16 g_W2L[(size_t)Gz * Hz];    // 2 MiB: w_hh lo
// Published hidden state, K-quartered for incremental hand-off:
// [pingpong][bg][plane hi/lo][quarter][16 b][136 cols] (128 data + 8 pad)
__device__ __align__(16) __nv_bfloat16 g_HT3[2][4][2][4][16][136];
// Per-(bg,quarter) monotonic counters, each on its own 256B line.
__device__ unsigned g_cntq[16 * 64];

// ---------------- async-copy / mma helpers ----------------
__device__ __forceinline__ void cp_async16(void* dst_smem, const void* src_gmem) {
    unsigned d = (unsigned)__cvta_generic_to_shared(dst_smem);
    asm volatile("cp.async.cg.shared.global [%0], [%1], 16;\n"
                 :: "r"(d), "l"(src_gmem));
}
#define CP_COMMIT() asm volatile("cp.async.commit_group;\n" ::: "memory")
#define CP_WAIT0()  asm volatile("cp.async.wait_group 0;\n" ::: "memory")
#define CP_WAIT1()  asm volatile("cp.async.wait_group 1;\n" ::: "memory")

__device__ __forceinline__ void ldsm4(uint32_t* r, const __nv_bfloat16* p) {
    uint32_t a = (uint32_t)__cvta_generic_to_shared(p);
    asm volatile("ldmatrix.sync.aligned.m8n8.x4.shared.b16 {%0,%1,%2,%3}, [%4];"
                 : "=r"(r[0]), "=r"(r[1]), "=r"(r[2]), "=r"(r[3]) : "r"(a));
}

__device__ __forceinline__ void mma16816(float* d, const uint32_t* a, const uint32_t* b) {
    asm volatile(
        "mma.sync.aligned.m16n8k16.row.col.f32.bf16.bf16.f32 "
        "{%0,%1,%2,%3}, {%4,%5,%6,%7}, {%8,%9}, {%0,%1,%2,%3};"
        : "+f"(d[0]), "+f"(d[1]), "+f"(d[2]), "+f"(d[3])
        : "r"(a[0]), "r"(a[1]), "r"(a[2]), "r"(a[3]), "r"(b[0]), "r"(b[1]));
}

__device__ __forceinline__ void mbar_wait(unsigned mbar, unsigned ph) {
    unsigned done;
    asm volatile(
        "{\n\t.reg .pred P;\n\t"
        "mbarrier.try_wait.parity.acquire.cta.shared::cta.b64 P, [%1], %2;\n\t"
        "selp.b32 %0, 1, 0, P;\n\t}"
        : "=r"(done) : "r"(mbar), "r"(ph) : "memory");
    if (!done) {
        asm volatile(
            "{\n\t.reg .pred P1;\n\t"
            "WL%=:\n\t"
            "mbarrier.try_wait.parity.acquire.cta.shared::cta.b64 P1, [%0], %1;\n\t"
            "@P1 bra.uni WD%=;\n\t"
            "bra.uni WL%=;\n\t"
            "WD%=:\n\t}"
            :: "r"(mbar), "r"(ph) : "memory");
    }
}

// poll a monotonic counter (acquire) until >= target, then arm+issue one
// quarter's hi/lo bulk copies. Executed by lanes 0..3 of warp 0 (ITS lets
// each lane progress independently).
__device__ __forceinline__ void poll_issue_quarter(
    unsigned* cnt, unsigned target,
    unsigned mbar_hi, unsigned mbar_lo,
    unsigned dst_hi, unsigned dst_lo,
    const void* src_hi, const void* src_lo, unsigned bytes)
{
    unsigned v;
    do {
        asm volatile("ld.acquire.gpu.u32 %0, [%1];" : "=r"(v) : "l"(cnt) : "memory");
    } while (v < target);
    asm volatile("mbarrier.arrive.expect_tx.shared.b64 _, [%0], %1;"
                 :: "r"(mbar_hi), "r"(bytes) : "memory");
    asm volatile("cp.async.bulk.shared::cta.global.mbarrier::complete_tx::bytes "
                 "[%0], [%1], %2, [%3];"
                 :: "r"(dst_hi), "l"(src_hi), "r"(bytes), "r"(mbar_hi) : "memory");
    asm volatile("mbarrier.arrive.expect_tx.shared.b64 _, [%0], %1;"
                 :: "r"(mbar_lo), "r"(bytes) : "memory");
    asm volatile("cp.async.bulk.shared::cta.global.mbarrier::complete_tx::bytes "
                 "[%0], [%1], %2, [%3];"
                 :: "r"(dst_lo), "l"(src_lo), "r"(bytes), "r"(mbar_lo) : "memory");
}

// ---------------- fast transcendentals (MUFU EX2 path) ----------------
__device__ __forceinline__ float fsig(float x) {
    return __fdividef(1.0f, 1.0f + __expf(-x));
}
__device__ __forceinline__ float ftanh(float x) {
    return __fmaf_rn(2.0f, __fdividef(1.0f, 1.0f + __expf(-2.0f * x)), -1.0f);
}

// ---------------- fp32 -> bf16 hi/lo split ----------------
__global__ __launch_bounds__(256) void split_kernel(
    const float4* __restrict__ src,
    __nv_bfloat162* __restrict__ hi, __nv_bfloat162* __restrict__ lo, int n4)
{
    int i = blockIdx.x * blockDim.x + threadIdx.x;
    if (i >= n4) return;
    float4 v = src[i];
    float xs[4] = {v.x, v.y, v.z, v.w};
    __nv_bfloat16 h[4], l[4];
#pragma unroll
    for (int k = 0; k < 4; k++) {
        h[k] = __float2bfloat16(xs[k]);
        l[k] = __float2bfloat16(xs[k] - __bfloat162float(h[k]));
    }
    __nv_bfloat162 h0; h0.x = h[0]; h0.y = h[1];
    __nv_bfloat162 h1; h1.x = h[2]; h1.y = h[3];
    __nv_bfloat162 l0; l0.x = l[0]; l0.y = l[1];
    __nv_bfloat162 l1; l1.x = l[2]; l1.y = l[3];
    hi[2 * i] = h0; hi[2 * i + 1] = h1;
    lo[2 * i] = l0; lo[2 * i + 1] = l1;
}

// ---------------- tensor-core input-projection GEMM (validated R8) ----------------
__global__ void __launch_bounds__(256, 1) gemm_tc(
    float* __restrict__ C,
    const __nv_bfloat16* __restrict__ Ah, const __nv_bfloat16* __restrict__ Al,
    const __nv_bfloat16* __restrict__ Wh, const __nv_bfloat16* __restrict__ Wl,
    int K, const float* __restrict__ bias0, const float* __restrict__ bias1)
{
    extern __shared__ __nv_bfloat16 sm[];
    const int ARR = 128 * 40;
    const int STG = 4 * ARR;
    const int tid = threadIdx.x;
    const int lane = tid & 31, wid = tid >> 5;
    const int wm = wid & 1, wn = wid >> 1;
    const int bn = blockIdx.x, bm = blockIdx.y;

    const __nv_bfloat16* g0 = Ah + (size_t)(bm * 128) * K;
    const __nv_bfloat16* g1 = Al + (size_t)(bm * 128) * K;
    const __nv_bfloat16* g2 = Wh + (size_t)(bn * 128) * K;
    const __nv_bfloat16* g3 = Wl + (size_t)(bn * 128) * K;
    const __nv_bfloat16* gsrc[4] = {g0, g1, g2, g3};

    const int l_r = tid >> 2;
    const int l_c = tid & 3;

#define LOAD_STAGE(buf, kt)                                                     \
    {                                                                           \
        _Pragma("unroll")                                                       \
        for (int p = 0; p < 8; p++) {                                           \
            const int arr = p >> 1;                                             \
            const int r = (p & 1) * 64 + l_r;                                   \
            const void* s = gsrc[arr] + (size_t)r * K + (kt) + l_c * 8;         \
            void* d = (char*)(sm + (buf) * STG + arr * ARR + r * 40) + l_c * 16;\
            cp_async16(d, s);                                                   \
        }                                                                       \
        CP_COMMIT();                                                            \
    }

    float acc[4][4][4] = {};
    const int nk = K / 32;

    LOAD_STAGE(0, 0);

    const int a_lrow = (lane < 16) ? lane : lane - 16;
    const int a_cb = (lane < 16) ? 0 : 8;
    const int bgrp = lane >> 3, bwi = lane & 7;
    const int b_nrow = ((bgrp >= 2) ? 8 : 0) + bwi;
    const int b_koff = (bgrp & 1) ? 8 : 0;

    for (int it = 0; it < nk; it++) {
        if (it + 1 < nk) {
            LOAD_STAGE((it + 1) & 1, (it + 1) * 32);
            CP_WAIT1();
        } else {
            CP_WAIT0();
        }
        __syncthreads();
        const __nv_bfloat16* S = sm + (it & 1) * STG;

#pragma unroll
        for (int kk = 0; kk < 32; kk += 16) {
            uint32_t ah[4][4], al[4][4];
#pragma unroll
            for (int mt = 0; mt < 4; mt++) {
                int row = wm * 64 + mt * 16 + a_lrow;
                ldsm4(ah[mt], S + row * 40 + kk + a_cb);
                ldsm4(al[mt], S + ARR + row * 40 + kk + a_cb);
            }
            uint32_t bh[4][2], bl[4][2];
#pragma unroll
            for (int pr = 0; pr < 2; pr++) {
                int nrow = wn * 32 + pr * 16 + b_nrow;
                uint32_t r[4];
                ldsm4(r, S + 2 * ARR + nrow * 40 + kk + b_koff);
                bh[pr * 2][0] = r[0]; bh[pr * 2][1] = r[1];
                bh[pr * 2 + 1][0] = r[2]; bh[pr * 2 + 1][1] = r[3];
                ldsm4(r, S + 3 * ARR + nrow * 40 + kk + b_koff);
                bl[pr * 2][0] = r[0]; bl[pr * 2][1] = r[1];
                bl[pr * 2 + 1][0] = r[2]; bl[pr * 2 + 1][1] = r[3];
            }
#pragma unroll
            for (int mt = 0; mt < 4; mt++)
#pragma unroll
                for (int nt = 0; nt < 4; nt++) {
                    mma16816(acc[mt][nt], ah[mt], bh[nt]);
                    mma16816(acc[mt][nt], ah[mt], bl[nt]);
                    mma16816(acc[mt][nt], al[mt], bh[nt]);
                }
        }
        __syncthreads();
    }

    const int erow = lane >> 2, ecol = (lane & 3) * 2;
#pragma unroll
    for (int mt = 0; mt < 4; mt++) {
        int gr = bm * 128 + wm * 64 + mt * 16 + erow;
#pragma unroll
        for (int nt = 0; nt < 4; nt++) {
            int gc = bn * 128 + wn * 32 + nt * 8 + ecol;
            float b0v = bias0[gc] + bias1[gc];
            float b1v = bias0[gc + 1] + bias1[gc + 1];
            float2 v0 = make_float2(acc[mt][nt][0] + b0v, acc[mt][nt][1] + b1v);
            float2 v1 = make_float2(acc[mt][nt][2] + b0v, acc[mt][nt][3] + b1v);
            *(float2*)(C + (size_t)gr * Gz + gc) = v0;
            *(float2*)(C + (size_t)(gr + 8) * Gz + gc) = v1;
        }
    }
#undef LOAD_STAGE
}

// ---------------- tensor-core persistent LSTM layer ----------------
// 128 blocks x 512 threads (16 warps). Block (bg = bid>>5, jg = bid&31) owns
// batches [bg*16,+16) x j-cols [jg*16,+16). Warp (kh = wid&3, ng = wid>>2).
// Incremental per-quarter hand-off: producer releases its (bg, jg>>3) counter
// after publishing; lanes 0..3 of warp 0 poll quarters 0..3 independently and
// issue that quarter's hi/lo 4.35KB bulk copies; warp kh waits only on its own
// quarter's mbarrier, so early quarters compute while stragglers publish.
__global__ void __launch_bounds__(PNT, 1) lstm_layer_tc(
    const __nv_bfloat16* __restrict__ wqh,   // [2048][512] w_hh hi
    const __nv_bfloat16* __restrict__ wql,   // lo
    const float* __restrict__ xg,            // [B*T][2048] (+biases)
    const float* __restrict__ hxl, const float* __restrict__ cxl,
    __nv_bfloat16* __restrict__ hseq_hi,     // [B*T][512] or nullptr
    __nv_bfloat16* __restrict__ hseq_lo,
    float* __restrict__ hn_out, float* __restrict__ cn_out)
{
    extern __shared__ __nv_bfloat16 sm[];
    __nv_bfloat16* w_hi = sm;                 // [64 q][520]
    __nv_bfloat16* w_lo = sm + 64 * 520;
    __nv_bfloat16* h_hi = sm + 128 * 520;     // [4 qr][16 b][136]
    __nv_bfloat16* h_lo = h_hi + 4 * 16 * 136;
    float* acc_s = (float*)(h_lo + 4 * 16 * 136);  // [4 kh][64 q][16 b]
    __nv_bfloat16* pub_s = (__nv_bfloat16*)(acc_s + 4 * 64 * 16); // [2][16][16]

    __shared__ __align__(16) unsigned long long s_mbar[8];  // hi[0..3], lo[4..7]

    const int tid = threadIdx.x;
    const int bid = blockIdx.x;
    const int bg = bid >> 5;
    const int jg = bid & 31;
    const int lane = tid & 31, wid = tid >> 5;
    const int kh = wid & 3, ng = wid >> 2;
    const int myq = jg >> 3;                  // quarter this block produces

    unsigned* cnt_own = &g_cntq[(bg * 4 + myq) * 64];

    const unsigned QBYTES = 16 * 136 * 2;     // 4352 B per quarter per plane

    unsigned mb_hi[4], mb_lo[4], hd_hi[4], hd_lo[4];
#pragma unroll
    for (int q = 0; q < 4; q++) {
        mb_hi[q] = (unsigned)__cvta_generic_to_shared(&s_mbar[q]);
        mb_lo[q] = (unsigned)__cvta_generic_to_shared(&s_mbar[4 + q]);
        hd_hi[q] = (unsigned)__cvta_generic_to_shared(h_hi + q * 16 * 136);
        hd_lo[q] = (unsigned)__cvta_generic_to_shared(h_lo + q * 16 * 136);
    }

    if (tid < 8) {
        asm volatile("mbarrier.init.shared.b64 [%0], 1;"
                     :: "r"((unsigned)__cvta_generic_to_shared(&s_mbar[tid])) : "memory");
    }

    // ---- load w_hh slice (hi+lo) via cp.async: one-time ----
    for (int i = tid; i < 8192; i += PNT) {
        int arr = i >> 12;
        int idx = i & 4095;
        int q = idx >> 6, c = idx & 63;
        int gr = (q >> 4) * 512 + jg * 16 + (q & 15);
        const __nv_bfloat16* src = (arr ? wql : wqh) + (size_t)gr * Hz + c * 8;
        __nv_bfloat16* dst = (arr ? w_lo : w_hi) + q * 520 + c * 8;
        cp_async16(dst, src);
    }
    CP_COMMIT();

    // ---- cell identity + init state; publish h0 into quartered buffer ----
    const int b_loc = tid & 15, jj = (tid >> 4) & 15;
    const int b_glob = bg * 16 + b_loc;
    const int j_glob = jg * 16 + jj;
    const int qcol = (jg & 7) * 16 + jj;      // col within my quarter
    float c_reg = 0.0f;
    if (tid < 256) {
        c_reg = cxl[b_glob * Hz + j_glob];
        float h0 = hxl[b_glob * Hz + j_glob];
        __nv_bfloat16 hh0 = __float2bfloat16(h0);
        __nv_bfloat16 hl0 = __float2bfloat16(h0 - __bfloat162float(hh0));
        g_HT3[0][bg][0][myq][b_loc][qcol] = hh0;
        g_HT3[0][bg][1][myq][b_loc][qcol] = hl0;
    }
    CP_WAIT0();

    // ---- initial round: release own quarter, poll+issue all quarters ----
    unsigned nbar = 1;
    __syncthreads();
    if (tid == 0) {
        asm volatile("red.release.gpu.global.add.u32 [%0], %1;"
                     :: "l"(cnt_own), "r"(1u) : "memory");
    }
    if (tid < 4) {
        poll_issue_quarter(&g_cntq[(bg * 4 + tid) * 64], nbar * QPROD,
                           mb_hi[tid], mb_lo[tid], hd_hi[tid], hd_lo[tid],
                           &g_HT3[0][bg][0][tid][0][0],
                           &g_HT3[0][bg][1][tid][0][0], QBYTES);
    }
    __syncthreads();     // also orders the w-smem fill before whf preload

    // ---- fragment identities (identical to validated gemm_tc) ----
    const int a_lrow = (lane < 16) ? lane : lane - 16;
    const int a_cb = (lane < 16) ? 0 : 8;
    const int bgrp = lane >> 3, bwi = lane & 7;
    const int b_nrow = ((bgrp >= 2) ? 8 : 0) + bwi;
    const int b_koff = (bgrp & 1) ? 8 : 0;
    const int erow = lane >> 2, ecol = (lane & 3) * 2;

    const __nv_bfloat16* wrow_hi = w_hi + (ng * 16 + b_nrow) * 520 + b_koff;
    const __nv_bfloat16* wrow_lo = w_lo + (ng * 16 + b_nrow) * 520 + b_koff;
    // this warp reads only its own quarter's h rows
    const __nv_bfloat16* arow_hi = h_hi + kh * 16 * 136 + a_lrow * 136 + a_cb;
    const __nv_bfloat16* arow_lo = h_lo + kh * 16 * 136 + a_lrow * 136 + a_cb;

    const int kbase = kh * 128;

    // ---- preload loop-invariant w-hi fragments into registers ----
    uint32_t whf[8][4];
#pragma unroll
    for (int ks = 0; ks < 8; ks++)
        ldsm4(whf[ks], wrow_hi + kbase + ks * 16);

    float hlast = 0.0f;
    unsigned ph = 0;

    for (int t = 0; t < Tz; t++) {
        const int p = t & 1;

        // ---- prefetch xg for cell threads (overlaps in-flight copies) ----
        float xp[4];
        if (tid < 256) {
#pragma unroll
            for (int g = 0; g < 4; g++)
                xp[g] = xg[((size_t)b_glob * Tz + t) * Gz + g * 512 + j_glob];
        }

        float acc0[4] = {}, acc1[4] = {};
        uint32_t ahf[8][4];

        // ---- pass 1: ah * bh (own quarter hi; w-hi in regs) ----
        mbar_wait(mb_hi[kh], ph);
#pragma unroll
        for (int ks = 0; ks < 8; ks++) {
            ldsm4(ahf[ks], arow_hi + ks * 16);
            mma16816(acc0, ahf[ks], &whf[ks][0]);
            mma16816(acc1, ahf[ks], &whf[ks][2]);
        }

        // ---- pass 2: al * bh + ah * bl (own quarter lo) ----
        mbar_wait(mb_lo[kh], ph);
        ph ^= 1;
#pragma unroll
        for (int ks = 0; ks < 8; ks++) {
            uint32_t al[4], rl[4];
            ldsm4(al, arow_lo + ks * 16);
            ldsm4(rl, wrow_lo + kbase + ks * 16);
            uint32_t bl0[2] = {rl[0], rl[1]}, bl1[2] = {rl[2], rl[3]};
            mma16816(acc0, al, &whf[ks][0]);
            mma16816(acc1, al, &whf[ks][2]);
            mma16816(acc0, ahf[ks], bl0);
            mma16816(acc1, ahf[ks], bl1);
        }

        // ---- stash K-quarter partials: acc_s[kh][q][b] ----
        {
            int q0 = ng * 16 + ecol;
            acc_s[(kh * 64 + q0) * 16 + erow]         = acc0[0];
            acc_s[(kh * 64 + q0 + 1) * 16 + erow]     = acc0[1];
            acc_s[(kh * 64 + q0) * 16 + erow + 8]     = acc0[2];
            acc_s[(kh * 64 + q0 + 1) * 16 + erow + 8] = acc0[3];
            int q1 = ng * 16 + 8 + ecol;
            acc_s[(kh * 64 + q1) * 16 + erow]         = acc1[0];
            acc_s[(kh * 64 + q1 + 1) * 16 + erow]     = acc1[1];
            acc_s[(kh * 64 + q1) * 16 + erow + 8]     = acc1[2];
            acc_s[(kh * 64 + q1 + 1) * 16 + erow + 8] = acc1[3];
        }
        __syncthreads();

        // ---- cell update (threads 0..255): fast gates, stage publish ----
        __nv_bfloat16 hh, hl;
        if (tid < 256) {
            float gv[4];
#pragma unroll
            for (int g = 0; g < 4; g++) {
                int q = g * 16 + jj;
                float s = xp[g];
#pragma unroll
                for (int z = 0; z < 4; z++)
                    s += acc_s[(z * 64 + q) * 16 + b_loc];
                gv[g] = s;
            }
            float ig = fsig(gv[0]);
            float fg = fsig(gv[1]);
            float gg = ftanh(gv[2]);
            float og = fsig(gv[3]);
            c_reg = fg * c_reg + ig * gg;
            float hnew = og * ftanh(c_reg);
            hlast = hnew;
            hh = __float2bfloat16(hnew);
            hl = __float2bfloat16(hnew - __bfloat162float(hh));
            pub_s[(0 * 16 + b_loc) * 16 + jj] = hh;
            pub_s[(1 * 16 + b_loc) * 16 + jj] = hl;
        }
        __syncthreads();

        // ---- coalesced publish: 64 x STG.128 into quartered layout ----
        if (tid < 64) {
            int plane = tid >> 5;
            int b = (tid >> 1) & 15;
            int half = tid & 1;
            uint4 v = *(uint4*)(pub_s + plane * 256 + b * 16 + half * 8);
            *(uint4*)(&g_HT3[p ^ 1][bg][plane][myq][b][(jg & 7) * 16 + half * 8]) = v;
        }

        // ---- release own quarter + per-lane poll/issue for next round ----
        if (t < Tz - 1) {
            nbar++;
            __syncthreads();        // publish visible before release
            if (tid == 0) {
                asm volatile("red.release.gpu.global.add.u32 [%0], %1;"
                             :: "l"(cnt_own), "r"(1u) : "memory");
            }
            if (tid < 4) {
                poll_issue_quarter(&g_cntq[(bg * 4 + tid) * 64], nbar * QPROD,
                                   mb_hi[tid], mb_lo[tid], hd_hi[tid], hd_lo[tid],
                                   &g_HT3[p ^ 1][bg][0][tid][0][0],
                                   &g_HT3[p ^ 1][bg][1][tid][0][0], QBYTES);
            }
            // other warps fall through to next iteration's mbar_wait
        }

        // ---- hseq store (off the release path) ----
        if (hseq_hi && tid < 256) {
            size_t off = ((size_t)b_glob * Tz + t) * Hz + j_glob;
            hseq_hi[off] = hh;
            hseq_lo[off] = hl;
        }
    }

    if (tid < 256) {
        hn_out[b_glob * Hz + j_glob] = hlast;
        cn_out[b_glob * Hz + j_glob] = c_reg;
    }

    if (tid < 8) {
        asm volatile("mbarrier.inval.shared.b64 [%0];"
                     :: "r"((unsigned)__cvta_generic_to_shared(&s_mbar[tid])) : "memory");
    }

    // ---- exit protocol: restore counters to 0 for graph replay ----
    // Releases per counter: 512 rounds x 8 producers = 4096. Each block adds
    // one exit arrival (+8). First producer of each quarter resets.
    __syncthreads();
    if (tid == 0) {
        atomicAdd(cnt_own, 1u);
        if ((jg & 7) == 0) {
            const unsigned exit_target = 512u * QPROD + QPROD;   // 4104
            unsigned v;
            do {
                asm volatile("ld.acquire.gpu.u32 %0, [%1];" : "=r"(v) : "l"(cnt_own) : "memory");
            } while (v < exit_target);
            asm volatile("st.relaxed.gpu.u32 [%0], %1;" :: "l"(cnt_own), "r"(0u) : "memory");
        }
    }
}

// ---------------- FC head ----------------
__global__ __launch_bounds__(256) void fc_kernel(
    float* __restrict__ out, const float* __restrict__ h,
    const float* __restrict__ w, const float* __restrict__ bb)
{
    int b = blockIdx.x;
    float s = 0.0f;
    for (int k = threadIdx.x; k < Hz; k += blockDim.x)
        s += h[(size_t)b * Hz + k] * w[k];
#pragma unroll
    for (int o = 16; o > 0; o >>= 1)
        s += __shfl_xor_sync(0xFFFFFFFFu, s, o);
    __shared__ float red[8];
    int wid = threadIdx.x >> 5, lane = threadIdx.x & 31;
    if (lane == 0) red[wid] = s;
    __syncthreads();
    if (threadIdx.x == 0) {
        float t = 0.0f;
#pragma unroll
        for (int i = 0; i < 8; i++) t += red[i];
        out[b] = t + bb[0];
    }
}

extern "C" void kernel_launch(void* const* d_in, const int* in_sizes, int n_in,
                              void* d_out, int out_size) {
    (void)in_sizes; (void)n_in; (void)out_size;
    const float* x    = (const float*)d_in[0];
    const float* hx   = (const float*)d_in[1];
    const float* cx   = (const float*)d_in[2];
    const float* wih0 = (const float*)d_in[3];
    const float* whh0 = (const float*)d_in[4];
    const float* bih0 = (const float*)d_in[5];
    const float* bhh0 = (const float*)d_in[6];
    const float* wih1 = (const float*)d_in[7];
    const float* whh1 = (const float*)d_in[8];
    const float* bih1 = (const float*)d_in[9];
    const float* bhh1 = (const float*)d_in[10];
    const float* fcw  = (const float*)d_in[11];
    const float* fcb  = (const float*)d_in[12];
    float* out = (float*)d_out;

    void *vXG, *vAH, *vAL, *vWH, *vWL, *vW2H, *vW2L;
    cudaGetSymbolAddress(&vXG, g_XG);
    cudaGetSymbolAddress(&vAH, g_AH);
    cudaGetSymbolAddress(&vAL, g_AL);
    cudaGetSymbolAddress(&vWH, g_WH);
    cudaGetSymbolAddress(&vWL, g_WL);
    cudaGetSymbolAddress(&vW2H, g_W2H);
    cudaGetSymbolAddress(&vW2L, g_W2L);
    float* XG = (float*)vXG;
    __nv_bfloat16* AH = (__nv_bfloat16*)vAH;
    __nv_bfloat16* AL = (__nv_bfloat16*)vAL;
    __nv_bfloat16* WH = (__nv_bfloat16*)vWH;
    __nv_bfloat16* WL = (__nv_bfloat16*)vWL;
    __nv_bfloat16* W2H = (__nv_bfloat16*)vW2H;
    __nv_bfloat16* W2L = (__nv_bfloat16*)vW2L;

    const int gemm_smem = 2 * 4 * 128 * 40 * (int)sizeof(__nv_bfloat16);   // 80 KB
    const int persist_smem = (2 * 64 * 520 + 2 * 4 * 16 * 136) * (int)sizeof(__nv_bfloat16)
                           + 4 * 64 * 16 * (int)sizeof(float)
                           + 2 * 16 * 16 * (int)sizeof(__nv_bfloat16);     // ~168 KB
    static bool attr_set = false;
    if (!attr_set) {
        cudaFuncSetAttribute(gemm_tc,
                             cudaFuncAttributeMaxDynamicSharedMemorySize, gemm_smem);
        cudaFuncSetAttribute(lstm_layer_tc,
                             cudaFuncAttributeMaxDynamicSharedMemorySize, persist_smem);
        attr_set = true;
    }

    // Output packing: [out(64) | hn(2*B*H) | cn(2*B*H)]
    float* hn = out + Bz;
    float* cn = out + Bz + 2 * BHs;

    // ---- Layer 0 ----
    {
        int n4 = (BTz * Iz) / 4;
        split_kernel<<<(n4 + 255) / 256, 256>>>(
            (const float4*)x, (__nv_bfloat162*)AH, (__nv_bfloat162*)AL, n4);
    }
    {
        int n4 = (Gz * Iz) / 4;
        split_kernel<<<(n4 + 255) / 256, 256>>>(
            (const float4*)wih0, (__nv_bfloat162*)WH, (__nv_bfloat162*)WL, n4);
    }
    {
        int n4 = (Gz * Hz) / 4;
        split_kernel<<<(n4 + 255) / 256, 256>>>(
            (const float4*)whh0, (__nv_bfloat162*)W2H, (__nv_bfloat162*)W2L, n4);
    }
    gemm_tc<<<dim3(Gz / 128, BTz / 128), 256, gemm_smem>>>(
        XG, AH, AL, WH, WL, Iz, bih0, bhh0);
    lstm_layer_tc<<<NBLK, PNT, persist_smem>>>(
        W2H, W2L, XG, hx, cx, AH, AL, hn, cn);   // hseq -> AH/AL for GEMM1

    // ---- Layer 1 ----
    {
        int n4 = (Gz * Hz) / 4;
        split_kernel<<<(n4 + 255) / 256, 256>>>(
            (const float4*)wih1, (__nv_bfloat162*)WH, (__nv_bfloat162*)WL, n4);
        split_kernel<<<(n4 + 255) / 256, 256>>>(
            (const float4*)whh1, (__nv_bfloat162*)W2H, (__nv_bfloat162*)W2L, n4);
    }
    gemm_tc<<<dim3(Gz / 128, BTz / 128), 256, gemm_smem>>>(
        XG, AH, AL, WH, WL, Hz, bih1, bhh1);
    lstm_layer_tc<<<NBLK, PNT, persist_smem>>>(
        W2H, W2L, XG, hx + BHs, cx + BHs, nullptr, nullptr, hn + BHs, cn + BHs);

    // ---- FC head ----
    fc_kernel<<<Bz, 256>>>(out, hn + BHs, fcw, fcb);
}

// round 17
// speedup vs baseline: 1.1080x; 1.0004x over previous
#include <cuda_runtime.h>
#include <cuda_bf16.h>
#include <cstdint>

#define Bz 64
#define Tz 512
#define Iz 128
#define Hz 512
#define Gz 2048          // 4*H
#define BTz (Bz*Tz)      // 32768
#define BHs (Bz*Hz)      // 32768

#define NBLK 128
#define PNT 512          // persistent kernel threads (16 warps)
#define QPROD 8          // producers per (bg, quarter)

// Scratch (static device globals)
__device__ float g_XG[(size_t)BTz * Gz];            // 256 MiB: gate projections
__device__ __nv_bfloat16 g_AH[(size_t)BTz * Hz];    // 32 MiB: A hi (x-split, then hseq)
__device__ __nv_bfloat16 g_AL[(size_t)BTz * Hz];    // 32 MiB: A lo
__device__ __nv_bfloat16 g_WH[(size_t)Gz * Hz];     // 2 MiB: w_ih hi
__device__ __nv_bfloat16 g_WL[(size_t)Gz * Hz];     // 2 MiB: w_ih lo
__device__ __nv_bfloat16 g_W2H[(size_t)Gz * Hz];    // 2 MiB: w_hh hi
__device__ __nv_bfloat16 g_W2L[(size_t)Gz * Hz];    // 2 MiB: w_hh lo
// Published hidden state, K-quartered for incremental hand-off:
// [pingpong][bg][plane hi/lo][quarter][16 b][136 cols] (128 data + 8 pad)
__device__ __align__(16) __nv_bfloat16 g_HT3[2][4][2][4][16][136];
// Per-(bg,quarter) monotonic counters, each on its own 256B line.
__device__ unsigned g_cntq[16 * 64];

// ---------------- async-copy / mma helpers ----------------
__device__ __forceinline__ void cp_async16(void* dst_smem, const void* src_gmem) {
    unsigned d = (unsigned)__cvta_generic_to_shared(dst_smem);
    asm volatile("cp.async.cg.shared.global [%0], [%1], 16;\n"
                 :: "r"(d), "l"(src_gmem));
}
#define CP_COMMIT() asm volatile("cp.async.commit_group;\n" ::: "memory")
#define CP_WAIT0()  asm volatile("cp.async.wait_group 0;\n" ::: "memory")
#define CP_WAIT1()  asm volatile("cp.async.wait_group 1;\n" ::: "memory")

__device__ __forceinline__ void ldsm4(uint32_t* r, const __nv_bfloat16* p) {
    uint32_t a = (uint32_t)__cvta_generic_to_shared(p);
    asm volatile("ldmatrix.sync.aligned.m8n8.x4.shared.b16 {%0,%1,%2,%3}, [%4];"
                 : "=r"(r[0]), "=r"(r[1]), "=r"(r[2]), "=r"(r[3]) : "r"(a));
}

__device__ __forceinline__ void mma16816(float* d, const uint32_t* a, const uint32_t* b) {
    asm volatile(
        "mma.sync.aligned.m16n8k16.row.col.f32.bf16.bf16.f32 "
        "{%0,%1,%2,%3}, {%4,%5,%6,%7}, {%8,%9}, {%0,%1,%2,%3};"
        : "+f"(d[0]), "+f"(d[1]), "+f"(d[2]), "+f"(d[3])
        : "r"(a[0]), "r"(a[1]), "r"(a[2]), "r"(a[3]), "r"(b[0]), "r"(b[1]));
}

__device__ __forceinline__ void mbar_wait(unsigned mbar, unsigned ph) {
    unsigned done;
    asm volatile(
        "{\n\t.reg .pred P;\n\t"
        "mbarrier.try_wait.parity.acquire.cta.shared::cta.b64 P, [%1], %2;\n\t"
        "selp.b32 %0, 1, 0, P;\n\t}"
        : "=r"(done) : "r"(mbar), "r"(ph) : "memory");
    if (!done) {
        asm volatile(
            "{\n\t.reg .pred P1;\n\t"
            "WL%=:\n\t"
            "mbarrier.try_wait.parity.acquire.cta.shared::cta.b64 P1, [%0], %1;\n\t"
            "@P1 bra.uni WD%=;\n\t"
            "bra.uni WL%=;\n\t"
            "WD%=:\n\t}"
            :: "r"(mbar), "r"(ph) : "memory");
    }
}

// poll a monotonic counter (acquire) until >= target, then arm+issue one
// quarter's hi/lo bulk copies. Executed by lanes 0..3 of warp 0 (ITS lets
// each lane progress). [R15-proven]
__device__ __forceinline__ void poll_issue_quarter(
    unsigned* cnt, unsigned target,
    unsigned mbar_hi, unsigned mbar_lo,
    unsigned dst_hi, unsigned dst_lo,
    const void* src_hi, const void* src_lo, unsigned bytes)
{
    unsigned v;
    do {
        asm volatile("ld.acquire.gpu.u32 %0, [%1];" : "=r"(v) : "l"(cnt) : "memory");
    } while (v < target);
    asm volatile("mbarrier.arrive.expect_tx.shared.b64 _, [%0], %1;"
                 :: "r"(mbar_hi), "r"(bytes) : "memory");
    asm volatile("cp.async.bulk.shared::cta.global.mbarrier::complete_tx::bytes "
                 "[%0], [%1], %2, [%3];"
                 :: "r"(dst_hi), "l"(src_hi), "r"(bytes), "r"(mbar_hi) : "memory");
    asm volatile("mbarrier.arrive.expect_tx.shared.b64 _, [%0], %1;"
                 :: "r"(mbar_lo), "r"(bytes) : "memory");
    asm volatile("cp.async.bulk.shared::cta.global.mbarrier::complete_tx::bytes "
                 "[%0], [%1], %2, [%3];"
                 :: "r"(dst_lo), "l"(src_lo), "r"(bytes), "r"(mbar_lo) : "memory");
}

// ---------------- fast transcendentals (MUFU EX2 path) ----------------
__device__ __forceinline__ float fsig(float x) {
    return __fdividef(1.0f, 1.0f + __expf(-x));
}
__device__ __forceinline__ float ftanh(float x) {
    return __fmaf_rn(2.0f, __fdividef(1.0f, 1.0f + __expf(-2.0f * x)), -1.0f);
}

// ---------------- fp32 -> bf16 hi/lo split ----------------
__global__ __launch_bounds__(256) void split_kernel(
    const float4* __restrict__ src,
    __nv_bfloat162* __restrict__ hi, __nv_bfloat162* __restrict__ lo, int n4)
{
    int i = blockIdx.x * blockDim.x + threadIdx.x;
    if (i >= n4) return;
    float4 v = src[i];
    float xs[4] = {v.x, v.y, v.z, v.w};
    __nv_bfloat16 h[4], l[4];
#pragma unroll
    for (int k = 0; k < 4; k++) {
        h[k] = __float2bfloat16(xs[k]);
        l[k] = __float2bfloat16(xs[k] - __bfloat162float(h[k]));
    }
    __nv_bfloat162 h0; h0.x = h[0]; h0.y = h[1];
    __nv_bfloat162 h1; h1.x = h[2]; h1.y = h[3];
    __nv_bfloat162 l0; l0.x = l[0]; l0.y = l[1];
    __nv_bfloat162 l1; l1.x = l[2]; l1.y = l[3];
    hi[2 * i] = h0; hi[2 * i + 1] = h1;
    lo[2 * i] = l0; lo[2 * i + 1] = l1;
}

// ---------------- tensor-core input-projection GEMM (validated R8) ----------------
__global__ void __launch_bounds__(256, 1) gemm_tc(
    float* __restrict__ C,
    const __nv_bfloat16* __restrict__ Ah, const __nv_bfloat16* __restrict__ Al,
    const __nv_bfloat16* __restrict__ Wh, const __nv_bfloat16* __restrict__ Wl,
    int K, const float* __restrict__ bias0, const float* __restrict__ bias1)
{
    extern __shared__ __nv_bfloat16 sm[];
    const int ARR = 128 * 40;
    const int STG = 4 * ARR;
    const int tid = threadIdx.x;
    const int lane = tid & 31, wid = tid >> 5;
    const int wm = wid & 1, wn = wid >> 1;
    const int bn = blockIdx.x, bm = blockIdx.y;

    const __nv_bfloat16* g0 = Ah + (size_t)(bm * 128) * K;
    const __nv_bfloat16* g1 = Al + (size_t)(bm * 128) * K;
    const __nv_bfloat16* g2 = Wh + (size_t)(bn * 128) * K;
    const __nv_bfloat16* g3 = Wl + (size_t)(bn * 128) * K;
    const __nv_bfloat16* gsrc[4] = {g0, g1, g2, g3};

    const int l_r = tid >> 2;
    const int l_c = tid & 3;

#define LOAD_STAGE(buf, kt)                                                     \
    {                                                                           \
        _Pragma("unroll")                                                       \
        for (int p = 0; p < 8; p++) {                                           \
            const int arr = p >> 1;                                             \
            const int r = (p & 1) * 64 + l_r;                                   \
            const void* s = gsrc[arr] + (size_t)r * K + (kt) + l_c * 8;         \
            void* d = (char*)(sm + (buf) * STG + arr * ARR + r * 40) + l_c * 16;\
            cp_async16(d, s);                                                   \
        }                                                                       \
        CP_COMMIT();                                                            \
    }

    float acc[4][4][4] = {};
    const int nk = K / 32;

    LOAD_STAGE(0, 0);

    const int a_lrow = (lane < 16) ? lane : lane - 16;
    const int a_cb = (lane < 16) ? 0 : 8;
    const int bgrp = lane >> 3, bwi = lane & 7;
    const int b_nrow = ((bgrp >= 2) ? 8 : 0) + bwi;
    const int b_koff = (bgrp & 1) ? 8 : 0;

    for (int it = 0; it < nk; it++) {
        if (it + 1 < nk) {
            LOAD_STAGE((it + 1) & 1, (it + 1) * 32);
            CP_WAIT1();
        } else {
            CP_WAIT0();
        }
        __syncthreads();
        const __nv_bfloat16* S = sm + (it & 1) * STG;

#pragma unroll
        for (int kk = 0; kk < 32; kk += 16) {
            uint32_t ah[4][4], al[4][4];
#pragma unroll
            for (int mt = 0; mt < 4; mt++) {
                int row = wm * 64 + mt * 16 + a_lrow;
                ldsm4(ah[mt], S + row * 40 + kk + a_cb);
                ldsm4(al[mt], S + ARR + row * 40 + kk + a_cb);
            }
            uint32_t bh[4][2], bl[4][2];
#pragma unroll
            for (int pr = 0; pr < 2; pr++) {
                int nrow = wn * 32 + pr * 16 + b_nrow;
                uint32_t r[4];
                ldsm4(r, S + 2 * ARR + nrow * 40 + kk + b_koff);
                bh[pr * 2][0] = r[0]; bh[pr * 2][1] = r[1];
                bh[pr * 2 + 1][0] = r[2]; bh[pr * 2 + 1][1] = r[3];
                ldsm4(r, S + 3 * ARR + nrow * 40 + kk + b_koff);
                bl[pr * 2][0] = r[0]; bl[pr * 2][1] = r[1];
                bl[pr * 2 + 1][0] = r[2]; bl[pr * 2 + 1][1] = r[3];
            }
#pragma unroll
            for (int mt = 0; mt < 4; mt++)
#pragma unroll
                for (int nt = 0; nt < 4; nt++) {
                    mma16816(acc[mt][nt], ah[mt], bh[nt]);
                    mma16816(acc[mt][nt], ah[mt], bl[nt]);
                    mma16816(acc[mt][nt], al[mt], bh[nt]);
                }
        }
        __syncthreads();
    }

    const int erow = lane >> 2, ecol = (lane & 3) * 2;
#pragma unroll
    for (int mt = 0; mt < 4; mt++) {
        int gr = bm * 128 + wm * 64 + mt * 16 + erow;
#pragma unroll
        for (int nt = 0; nt < 4; nt++) {
            int gc = bn * 128 + wn * 32 + nt * 8 + ecol;
            float b0v = bias0[gc] + bias1[gc];
            float b1v = bias0[gc + 1] + bias1[gc + 1];
            float2 v0 = make_float2(acc[mt][nt][0] + b0v, acc[mt][nt][1] + b1v);
            float2 v1 = make_float2(acc[mt][nt][2] + b0v, acc[mt][nt][3] + b1v);
            *(float2*)(C + (size_t)gr * Gz + gc) = v0;
            *(float2*)(C + (size_t)(gr + 8) * Gz + gc) = v1;
        }
    }
#undef LOAD_STAGE
}

// ---------------- tensor-core persistent LSTM layer (R15-proven) ----------------
// 128 blocks x 512 threads (16 warps). Block (bg = bid>>5, jg = bid&31) owns
// batches [bg*16,+16) x j-cols [jg*16,+16). Warp (kh = wid&3, ng = wid>>2).
// Incremental per-quarter hand-off: producer red.release's its (bg, jg>>3)
// counter after publishing; lanes 0..3 of warp 0 poll quarters 0..3 with
// ld.acquire and issue that quarter's hi/lo 4.35KB bulk copies; warp kh waits
// only on its own quarter's mbarrier.
__global__ void __launch_bounds__(PNT, 1) lstm_layer_tc(
    const __nv_bfloat16* __restrict__ wqh,   // [2048][512] w_hh hi
    const __nv_bfloat16* __restrict__ wql,   // lo
    const float* __restrict__ xg,            // [B*T][2048] (+biases)
    const float* __restrict__ hxl, const float* __restrict__ cxl,
    __nv_bfloat16* __restrict__ hseq_hi,     // [B*T][512] or nullptr
    __nv_bfloat16* __restrict__ hseq_lo,
    float* __restrict__ hn_out, float* __restrict__ cn_out)
{
    extern __shared__ __nv_bfloat16 sm[];
    __nv_bfloat16* w_hi = sm;                 // [64 q][520]
    __nv_bfloat16* w_lo = sm + 64 * 520;
    __nv_bfloat16* h_hi = sm + 128 * 520;     // [4 qr][16 b][136]
    __nv_bfloat16* h_lo = h_hi + 4 * 16 * 136;
    float* acc_s = (float*)(h_lo + 4 * 16 * 136);  // [4 kh][64 q][16 b]
    __nv_bfloat16* pub_s = (__nv_bfloat16*)(acc_s + 4 * 64 * 16); // [2][16][16]

    __shared__ __align__(16) unsigned long long s_mbar[8];  // hi[0..3], lo[4..7]

    const int tid = threadIdx.x;
    const int bid = blockIdx.x;
    const int bg = bid >> 5;
    const int jg = bid & 31;
    const int lane = tid & 31, wid = tid >> 5;
    const int kh = wid & 3, ng = wid >> 2;
    const int myq = jg >> 3;                  // quarter this block produces

    unsigned* cnt_own = &g_cntq[(bg * 4 + myq) * 64];

    const unsigned QBYTES = 16 * 136 * 2;     // 4352 B per quarter per plane

    unsigned mb_hi[4], mb_lo[4], hd_hi[4], hd_lo[4];
#pragma unroll
    for (int q = 0; q < 4; q++) {
        mb_hi[q] = (unsigned)__cvta_generic_to_shared(&s_mbar[q]);
        mb_lo[q] = (unsigned)__cvta_generic_to_shared(&s_mbar[4 + q]);
        hd_hi[q] = (unsigned)__cvta_generic_to_shared(h_hi + q * 16 * 136);
        hd_lo[q] = (unsigned)__cvta_generic_to_shared(h_lo + q * 16 * 136);
    }

    if (tid < 8) {
        asm volatile("mbarrier.init.shared.b64 [%0], 1;"
                     :: "r"((unsigned)__cvta_generic_to_shared(&s_mbar[tid])) : "memory");
    }

    // ---- load w_hh slice (hi+lo) via cp.async: one-time ----
    for (int i = tid; i < 8192; i += PNT) {
        int arr = i >> 12;
        int idx = i & 4095;
        int q = idx >> 6, c = idx & 63;
        int gr = (q >> 4) * 512 + jg * 16 + (q & 15);
        const __nv_bfloat16* src = (arr ? wql : wqh) + (size_t)gr * Hz + c * 8;
        __nv_bfloat16* dst = (arr ? w_lo : w_hi) + q * 520 + c * 8;
        cp_async16(dst, src);
    }
    CP_COMMIT();

    // ---- cell identity + init state; publish h0 into quartered buffer ----
    const int b_loc = tid & 15, jj = (tid >> 4) & 15;
    const int b_glob = bg * 16 + b_loc;
    const int j_glob = jg * 16 + jj;
    const int qcol = (jg & 7) * 16 + jj;      // col within my quarter
    float c_reg = 0.0f;
    if (tid < 256) {
        c_reg = cxl[b_glob * Hz + j_glob];
        float h0 = hxl[b_glob * Hz + j_glob];
        __nv_bfloat16 hh0 = __float2bfloat16(h0);
        __nv_bfloat16 hl0 = __float2bfloat16(h0 - __bfloat162float(hh0));
        g_HT3[0][bg][0][myq][b_loc][qcol] = hh0;
        g_HT3[0][bg][1][myq][b_loc][qcol] = hl0;
    }
    CP_WAIT0();

    // ---- initial round: release own quarter, poll+issue all quarters ----
    unsigned nbar = 1;
    __syncthreads();
    if (tid == 0) {
        asm volatile("red.release.gpu.global.add.u32 [%0], %1;"
                     :: "l"(cnt_own), "r"(1u) : "memory");
    }
    if (tid < 4) {
        poll_issue_quarter(&g_cntq[(bg * 4 + tid) * 64], nbar * QPROD,
                           mb_hi[tid], mb_lo[tid], hd_hi[tid], hd_lo[tid],
                           &g_HT3[0][bg][0][tid][0][0],
                           &g_HT3[0][bg][1][tid][0][0], QBYTES);
    }
    __syncthreads();     // also orders the w-smem fill before whf preload

    // ---- fragment identities (identical to validated gemm_tc) ----
    const int a_lrow = (lane < 16) ? lane : lane - 16;
    const int a_cb = (lane < 16) ? 0 : 8;
    const int bgrp = lane >> 3, bwi = lane & 7;
    const int b_nrow = ((bgrp >= 2) ? 8 : 0) + bwi;
    const int b_koff = (bgrp & 1) ? 8 : 0;
    const int erow = lane >> 2, ecol = (lane & 3) * 2;

    const __nv_bfloat16* wrow_hi = w_hi + (ng * 16 + b_nrow) * 520 + b_koff;
    const __nv_bfloat16* wrow_lo = w_lo + (ng * 16 + b_nrow) * 520 + b_koff;
    // this warp reads only its own quarter's h rows
    const __nv_bfloat16* arow_hi = h_hi + kh * 16 * 136 + a_lrow * 136 + a_cb;
    const __nv_bfloat16* arow_lo = h_lo + kh * 16 * 136 + a_lrow * 136 + a_cb;

    const int kbase = kh * 128;

    // ---- preload loop-invariant w-hi fragments into registers ----
    uint32_t whf[8][4];
#pragma unroll
    for (int ks = 0; ks < 8; ks++)
        ldsm4(whf[ks], wrow_hi + kbase + ks * 16);

    float hlast = 0.0f;
    unsigned ph = 0;

    for (int t = 0; t < Tz; t++) {
        const int p = t & 1;

        // ---- prefetch xg for cell threads (overlaps in-flight copies) ----
        float xp[4];
        if (tid < 256) {
#pragma unroll
            for (int g = 0; g < 4; g++)
                xp[g] = xg[((size_t)b_glob * Tz + t) * Gz + g * 512 + j_glob];
        }

        float acc0[4] = {}, acc1[4] = {};
        uint32_t ahf[8][4];

        // ---- pass 1: ah * bh (own quarter hi; w-hi in regs) ----
        mbar_wait(mb_hi[kh], ph);
#pragma unroll
        for (int ks = 0; ks < 8; ks++) {
            ldsm4(ahf[ks], arow_hi + ks * 16);
            mma16816(acc0, ahf[ks], &whf[ks][0]);
            mma16816(acc1, ahf[ks], &whf[ks][2]);
        }

        // ---- pass 2: al * bh + ah * bl (own quarter lo) ----
        mbar_wait(mb_lo[kh], ph);
        ph ^= 1;
#pragma unroll
        for (int ks = 0; ks < 8; ks++) {
            uint32_t al[4], rl[4];
            ldsm4(al, arow_lo + ks * 16);
            ldsm4(rl, wrow_lo + kbase + ks * 16);
            uint32_t bl0[2] = {rl[0], rl[1]}, bl1[2] = {rl[2], rl[3]};
            mma16816(acc0, al, &whf[ks][0]);
            mma16816(acc1, al, &whf[ks][2]);
            mma16816(acc0, ahf[ks], bl0);
            mma16816(acc1, ahf[ks], bl1);
        }

        // ---- stash K-quarter partials: acc_s[kh][q][b] ----
        {
            int q0 = ng * 16 + ecol;
            acc_s[(kh * 64 + q0) * 16 + erow]         = acc0[0];
            acc_s[(kh * 64 + q0 + 1) * 16 + erow]     = acc0[1];
            acc_s[(kh * 64 + q0) * 16 + erow + 8]     = acc0[2];
            acc_s[(kh * 64 + q0 + 1) * 16 + erow + 8] = acc0[3];
            int q1 = ng * 16 + 8 + ecol;
            acc_s[(kh * 64 + q1) * 16 + erow]         = acc1[0];
            acc_s[(kh * 64 + q1 + 1) * 16 + erow]     = acc1[1];
            acc_s[(kh * 64 + q1) * 16 + erow + 8]     = acc1[2];
            acc_s[(kh * 64 + q1 + 1) * 16 + erow + 8] = acc1[3];
        }
        __syncthreads();

        // ---- cell update (threads 0..255): fast gates, stage publish ----
        __nv_bfloat16 hh, hl;
        if (tid < 256) {
            float gv[4];
#pragma unroll
            for (int g = 0; g < 4; g++) {
                int q = g * 16 + jj;
                float s = xp[g];
#pragma unroll
                for (int z = 0; z < 4; z++)
                    s += acc_s[(z * 64 + q) * 16 + b_loc];
                gv[g] = s;
            }
            float ig = fsig(gv[0]);
            float fg = fsig(gv[1]);
            float gg = ftanh(gv[2]);
            float og = fsig(gv[3]);
            c_reg = fg * c_reg + ig * gg;
            float hnew = og * ftanh(c_reg);
            hlast = hnew;
            hh = __float2bfloat16(hnew);
            hl = __float2bfloat16(hnew - __bfloat162float(hh));
            pub_s[(0 * 16 + b_loc) * 16 + jj] = hh;
            pub_s[(1 * 16 + b_loc) * 16 + jj] = hl;
        }
        __syncthreads();

        // ---- coalesced publish: 64 x STG.128 into quartered layout ----
        if (tid < 64) {
            int plane = tid >> 5;
            int b = (tid >> 1) & 15;
            int half = tid & 1;
            uint4 v = *(uint4*)(pub_s + plane * 256 + b * 16 + half * 8);
            *(uint4*)(&g_HT3[p ^ 1][bg][plane][myq][b][(jg & 7) * 16 + half * 8]) = v;
        }

        // ---- release own quarter + per-lane poll/issue for next round ----
        if (t < Tz - 1) {
            nbar++;
            __syncthreads();        // publish visible before release
            if (tid == 0) {
                asm volatile("red.release.gpu.global.add.u32 [%0], %1;"
                             :: "l"(cnt_own), "r"(1u) : "memory");
            }
            if (tid < 4) {
                poll_issue_quarter(&g_cntq[(bg * 4 + tid) * 64], nbar * QPROD,
                                   mb_hi[tid], mb_lo[tid], hd_hi[tid], hd_lo[tid],
                                   &g_HT3[p ^ 1][bg][0][tid][0][0],
                                   &g_HT3[p ^ 1][bg][1][tid][0][0], QBYTES);
            }
            // other warps fall through to next iteration's mbar_wait
        }

        // ---- hseq store (off the release path) ----
        if (hseq_hi && tid < 256) {
            size_t off = ((size_t)b_glob * Tz + t) * Hz + j_glob;
            hseq_hi[off] = hh;
            hseq_lo[off] = hl;
        }
    }

    if (tid < 256) {
        hn_out[b_glob * Hz + j_glob] = hlast;
        cn_out[b_glob * Hz + j_glob] = c_reg;
    }

    if (tid < 8) {
        asm volatile("mbarrier.inval.shared.b64 [%0];"
                     :: "r"((unsigned)__cvta_generic_to_shared(&s_mbar[tid])) : "memory");
    }

    // ---- exit protocol: restore counters to 0 for graph replay ----
    // Releases per counter: 512 rounds x 8 producers = 4096. Each block adds
    // one exit arrival (+8). First producer of each quarter resets.
    __syncthreads();
    if (tid == 0) {
        atomicAdd(cnt_own, 1u);
        if ((jg & 7) == 0) {
            const unsigned exit_target = 512u * QPROD + QPROD;   // 4104
            unsigned v;
            do {
                asm volatile("ld.acquire.gpu.u32 %0, [%1];" : "=r"(v) : "l"(cnt_own) : "memory");
            } while (v < exit_target);
            asm volatile("st.relaxed.gpu.u32 [%0], %1;" :: "l"(cnt_own), "r"(0u) : "memory");
        }
    }
}

// ---------------- FC head ----------------
__global__ __launch_bounds__(256) void fc_kernel(
    float* __restrict__ out, const float* __restrict__ h,
    const float* __restrict__ w, const float* __restrict__ bb)
{
    int b = blockIdx.x;
    float s = 0.0f;
    for (int k = threadIdx.x; k < Hz; k += blockDim.x)
        s += h[(size_t)b * Hz + k] * w[k];
#pragma unroll
    for (int o = 16; o > 0; o >>= 1)
        s += __shfl_xor_sync(0xFFFFFFFFu, s, o);
    __shared__ float red[8];
    int wid = threadIdx.x >> 5, lane = threadIdx.x & 31;
    if (lane == 0) red[wid] = s;
    __syncthreads();
    if (threadIdx.x == 0) {
        float t = 0.0f;
#pragma unroll
        for (int i = 0; i < 8; i++) t += red[i];
        out[b] = t + bb[0];
    }
}

extern "C" void kernel_launch(void* const* d_in, const int* in_sizes, int n_in,
                              void* d_out, int out_size) {
    (void)in_sizes; (void)n_in; (void)out_size;
    const float* x    = (const float*)d_in[0];
    const float* hx   = (const float*)d_in[1];
    const float* cx   = (const float*)d_in[2];
    const float* wih0 = (const float*)d_in[3];
    const float* whh0 = (const float*)d_in[4];
    const float* bih0 = (const float*)d_in[5];
    const float* bhh0 = (const float*)d_in[6];
    const float* wih1 = (const float*)d_in[7];
    const float* whh1 = (const float*)d_in[8];
    const float* bih1 = (const float*)d_in[9];
    const float* bhh1 = (const float*)d_in[10];
    const float* fcw  = (const float*)d_in[11];
    const float* fcb  = (const float*)d_in[12];
    float* out = (float*)d_out;

    void *vXG, *vAH, *vAL, *vWH, *vWL, *vW2H, *vW2L;
    cudaGetSymbolAddress(&vXG, g_XG);
    cudaGetSymbolAddress(&vAH, g_AH);
    cudaGetSymbolAddress(&vAL, g_AL);
    cudaGetSymbolAddress(&vWH, g_WH);
    cudaGetSymbolAddress(&vWL, g_WL);
    cudaGetSymbolAddress(&vW2H, g_W2H);
    cudaGetSymbolAddress(&vW2L, g_W2L);
    float* XG = (float*)vXG;
    __nv_bfloat16* AH = (__nv_bfloat16*)vAH;
    __nv_bfloat16* AL = (__nv_bfloat16*)vAL;
    __nv_bfloat16* WH = (__nv_bfloat16*)vWH;
    __nv_bfloat16* WL = (__nv_bfloat16*)vWL;
    __nv_bfloat16* W2H = (__nv_bfloat16*)vW2H;
    __nv_bfloat16* W2L = (__nv_bfloat16*)vW2L;

    const int gemm_smem = 2 * 4 * 128 * 40 * (int)sizeof(__nv_bfloat16);   // 80 KB
    const int persist_smem = (2 * 64 * 520 + 2 * 4 * 16 * 136) * (int)sizeof(__nv_bfloat16)
                           + 4 * 64 * 16 * (int)sizeof(float)
                           + 2 * 16 * 16 * (int)sizeof(__nv_bfloat16);     // ~168 KB
    static bool attr_set = false;
    if (!attr_set) {
        cudaFuncSetAttribute(gemm_tc,
                             cudaFuncAttributeMaxDynamicSharedMemorySize, gemm_smem);
        cudaFuncSetAttribute(lstm_layer_tc,
                             cudaFuncAttributeMaxDynamicSharedMemorySize, persist_smem);
        attr_set = true;
    }

    // Output packing: [out(64) | hn(2*B*H) | cn(2*B*H)]
    float* hn = out + Bz;
    float* cn = out + Bz + 2 * BHs;

    // Launch order puts persist layer-0 at index 5 so the fixed ncu capture
    // (-s 5 -c 1) profiles the persistent kernel:
    //   0:split_x 1:split_wih0 2:split_whh0 3:gemm0 4:split_wih1
    //   5:persist0 6:split_whh1 7:gemm1 8:persist1 9:fc
    {
        int n4 = (BTz * Iz) / 4;                                 // 0
        split_kernel<<<(n4 + 255) / 256, 256>>>(
            (const float4*)x, (__nv_bfloat162*)AH, (__nv_bfloat162*)AL, n4);
    }
    {
        int n4 = (Gz * Iz) / 4;                                  // 1
        split_kernel<<<(n4 + 255) / 256, 256>>>(
            (const float4*)wih0, (__nv_bfloat162*)WH, (__nv_bfloat162*)WL, n4);
    }
    {
        int n4 = (Gz * Hz) / 4;                                  // 2
        split_kernel<<<(n4 + 255) / 256, 256>>>(
            (const float4*)whh0, (__nv_bfloat162*)W2H, (__nv_bfloat162*)W2L, n4);
    }
    gemm_tc<<<dim3(Gz / 128, BTz / 128), 256, gemm_smem>>>(      // 3
        XG, AH, AL, WH, WL, Iz, bih0, bhh0);
    {
        int n4 = (Gz * Hz) / 4;                                  // 4 (wih1 for gemm1)
        split_kernel<<<(n4 + 255) / 256, 256>>>(
            (const float4*)wih1, (__nv_bfloat162*)WH, (__nv_bfloat162*)WL, n4);
    }
    lstm_layer_tc<<<NBLK, PNT, persist_smem>>>(                  // 5  <- profiled
        W2H, W2L, XG, hx, cx, AH, AL, hn, cn);   // hseq -> AH/AL for GEMM1
    {
        int n4 = (Gz * Hz) / 4;                                  // 6
        split_kernel<<<(n4 + 255) / 256, 256>>>(
            (const float4*)whh1, (__nv_bfloat162*)W2H, (__nv_bfloat162*)W2L, n4);
    }
    gemm_tc<<<dim3(Gz / 128, BTz / 128), 256, gemm_smem>>>(      // 7
        XG, AH, AL, WH, WL, Hz, bih1, bhh1);
    lstm_layer_tc<<<NBLK, PNT, persist_smem>>>(                  // 8
        W2H, W2L, XG, hx + BHs, cx + BHs, nullptr, nullptr, hn + BHs, cn + BHs);
    fc_kernel<<<Bz, 256>>>(out, hn + BHs, fcw, fcb);             // 9
}